// round 4
// baseline (speedup 1.0000x reference)
#include <cuda_runtime.h>

// FeatureInteraction: B=16384, F=27, D=128
// out[b] = concat(embeddings[b].flatten() (3456), triu(E E^T, k=1) (351)) -> 3807 floats
//
// R4: scalar lane-coalesced streaming (LDG.32 -> swizzled STS.32 -> STG.32,
//     1 wavefront per 128B each, alignment-proof) replaces the float4 path
//     whose misaligned STG.32s cost 4x wavefronts. Triu results staged in
//     smem scratch then stored coalesced. Compute: XOR-swizzled LDS.128 +
//     packed fma.rn.f32x2, unchanged from R3.

static constexpr int F      = 27;
static constexpr int F_PAD  = 28;                 // pad to 4*7 for 4x4 tiles
static constexpr int D      = 128;
static constexpr int FLAT   = F * D;              // 3456
static constexpr int NPAIR  = (F * (F - 1)) / 2;  // 351
static constexpr int ROWLEN = FLAT + NPAIR;       // 3807
static constexpr int NB     = 3;                  // batch elements (warps) per block
static constexpr int THREADS = NB * 32;

__device__ __forceinline__ unsigned long long pack2(float x, float y) {
    unsigned long long r;
    asm("mov.b64 %0, {%1, %2};" : "=l"(r) : "f"(x), "f"(y));
    return r;
}
__device__ __forceinline__ void unpack2(unsigned long long v, float& x, float& y) {
    asm("mov.b64 {%0, %1}, %2;" : "=f"(x), "=f"(y) : "l"(v));
}
__device__ __forceinline__ void ffma2(unsigned long long& acc,
                                      unsigned long long a, unsigned long long b) {
    asm("fma.rn.f32x2 %0, %1, %2, %0;" : "+l"(acc) : "l"(a), "l"(b));
}

// smem layout: row f occupies words [f*128, f*128+128); within the row the
// 16B chunk c (d = 4c..4c+3) sits at chunk slot c ^ (f>>2). Word address:
__device__ __forceinline__ int sm_word(int f, int d) {
    return f * D + ((((d >> 2) ^ (f >> 2)) << 2) | (d & 3));
}

__global__ void __launch_bounds__(THREADS, 5)
fi_kernel(const float* __restrict__ in, float* __restrict__ out, int batch)
{
    __shared__ float sm[NB * F_PAD * D];          // 3*28*128*4 = 43008 B

    const int warp = threadIdx.x >> 5;
    const int lane = threadIdx.x & 31;
    const int b = blockIdx.x * NB + warp;
    if (b >= batch) return;

    const float* __restrict__ inb  = in  + (size_t)b * FLAT;
    float*       __restrict__ outb = out + (size_t)b * ROWLEN;
    float* smb = sm + warp * (F_PAD * D);

    // ---- Zero pad row 27 (read by edge tiles, never stored) ----
    *reinterpret_cast<float4*>(smb + 27 * D + (lane << 2)) =
        make_float4(0.f, 0.f, 0.f, 0.f);

    // ---- Streaming phase: scalar coalesced. Per iter: 128B in -> smem + out,
    // 3 wavefronts total (LDG.32, STS.32 conflict-free, STG.32 coalesced).
    #pragma unroll 9
    for (int it = 0; it < FLAT / 32; ++it) {       // 108 iters
        const int x = it * 32 + lane;              // 0..3455, lane-consecutive
        const float v = inb[x];
        smb[sm_word(x >> 7, x & 127)] = v;
        outb[x] = v;
    }
    __syncwarp();

    // ---- Compute: lane < 28 owns one 4x4 tile of the 7x7 tile grid over the
    // upper triangle of the 27x27 gram matrix. Per 16B chunk (4 d-values):
    // 8 LDS.128 (7 distinct addrs each, conflict-free) + 32 FFMA2.
    unsigned long long acc[4][4];
    int ti = 0, tj = 0;
    if (lane < 28) {
        int l = lane, cnt = 7;
        while (l >= cnt) { l -= cnt; ++ti; --cnt; }
        tj = ti + l;

        #pragma unroll
        for (int r = 0; r < 4; ++r)
            #pragma unroll
            for (int c = 0; c < 4; ++c) acc[r][c] = 0ull;

        const float* pi = smb + (4 * ti) * D;
        const float* pj = smb + (4 * tj) * D;

        #pragma unroll 2
        for (int c = 0; c < D / 4; ++c) {
            const int ci = (c ^ ti) << 2;
            const int cj = (c ^ tj) << 2;
            float4 ai4[4], aj4[4];
            #pragma unroll
            for (int r = 0; r < 4; ++r)
                ai4[r] = *reinterpret_cast<const float4*>(pi + r * D + ci);
            #pragma unroll
            for (int cc = 0; cc < 4; ++cc)
                aj4[cc] = *reinterpret_cast<const float4*>(pj + cc * D + cj);

            unsigned long long ailo[4], aihi[4], ajlo[4], ajhi[4];
            #pragma unroll
            for (int r = 0; r < 4; ++r) {
                ailo[r] = pack2(ai4[r].x, ai4[r].y);
                aihi[r] = pack2(ai4[r].z, ai4[r].w);
            }
            #pragma unroll
            for (int cc = 0; cc < 4; ++cc) {
                ajlo[cc] = pack2(aj4[cc].x, aj4[cc].y);
                ajhi[cc] = pack2(aj4[cc].z, aj4[cc].w);
            }
            #pragma unroll
            for (int r = 0; r < 4; ++r)
                #pragma unroll
                for (int cc = 0; cc < 4; ++cc) {
                    ffma2(acc[r][cc], ailo[r], ajlo[cc]);
                    ffma2(acc[r][cc], aihi[r], ajhi[cc]);
                }
        }
    }
    __syncwarp();   // all reads of smb rows done; rows become scratch

    // ---- Stage triu results in smem scratch, then store coalesced ----
    if (lane < 28) {
        #pragma unroll
        for (int r = 0; r < 4; ++r) {
            const int i = 4 * ti + r;
            #pragma unroll
            for (int cc = 0; cc < 4; ++cc) {
                const int j = 4 * tj + cc;
                if (i < j && j < F) {
                    float lo, hi;
                    unpack2(acc[r][cc], lo, hi);
                    const int off = i * F - (i * (i + 1)) / 2 + (j - i - 1);
                    smb[off] = lo + hi;
                }
            }
        }
    }
    __syncwarp();
    float* outp = outb + FLAT;
    #pragma unroll
    for (int it = 0; it < (NPAIR + 31) / 32; ++it) {  // 11 iters
        const int x = it * 32 + lane;
        if (x < NPAIR) outp[x] = smb[x];
    }
}

extern "C" void kernel_launch(void* const* d_in, const int* in_sizes, int n_in,
                              void* d_out, int out_size)
{
    const float* in = (const float*)d_in[0];
    float* out = (float*)d_out;
    const int batch = in_sizes[0] / FLAT;      // 16384
    const int grid = (batch + NB - 1) / NB;    // 5462
    fi_kernel<<<grid, THREADS>>>(in, out, batch);
}

// round 5
// speedup vs baseline: 1.0572x; 1.0572x over previous
#include <cuda_runtime.h>

// FeatureInteraction: B=16384, F=27, D=128
// out[b] = concat(embeddings[b].flatten() (3456), triu(E E^T, k=1) (351)) -> 3807 floats
//
// R5: 2 warps per batch element, split along d (each warp stages+computes its
//     own 64-wide d-half; one __syncthreads + smem partial reduction).
//     Doubles warps/SM at constant smem to attack the latency bound seen in R4.

static constexpr int F      = 27;
static constexpr int F_PAD  = 28;
static constexpr int D      = 128;
static constexpr int HALF   = 64;
static constexpr int FLAT   = F * D;              // 3456
static constexpr int NPAIR  = (F * (F - 1)) / 2;  // 351
static constexpr int ROWLEN = FLAT + NPAIR;       // 3807
static constexpr int NBATCH = 3;                  // batch elements per block
static constexpr int THREADS = NBATCH * 2 * 32;   // 192

__device__ __forceinline__ unsigned long long pack2(float x, float y) {
    unsigned long long r;
    asm("mov.b64 %0, {%1, %2};" : "=l"(r) : "f"(x), "f"(y));
    return r;
}
__device__ __forceinline__ void unpack2(unsigned long long v, float& x, float& y) {
    asm("mov.b64 {%0, %1}, %2;" : "=f"(x), "=f"(y) : "l"(v));
}
__device__ __forceinline__ void ffma2(unsigned long long& acc,
                                      unsigned long long a, unsigned long long b) {
    asm("fma.rn.f32x2 %0, %1, %2, %0;" : "+l"(acc) : "l"(a), "l"(b));
}

// Row f = words [f*128, f*128+128); 16B chunk c stored at slot c ^ (f>>2).
// Since f>>2 <= 6 the XOR stays inside c's 8-chunk octet, so each d-half
// [0,64) / [64,128) occupies exactly its own word range in every row.
__device__ __forceinline__ int sm_word(int f, int d) {
    return f * D + ((((d >> 2) ^ (f >> 2)) << 2) | (d & 3));
}

__global__ void __launch_bounds__(THREADS, 4)
fi_kernel(const float* __restrict__ in, float* __restrict__ out, int batch)
{
    __shared__ float sm[NBATCH * F_PAD * D];      // 43008 B

    const int tid  = threadIdx.x;
    const int warp = tid >> 5;
    const int lane = tid & 31;
    const int nb   = warp >> 1;                   // batch slot in block
    const int dh   = warp & 1;                    // d-half owned by this warp
    const int b    = blockIdx.x * NBATCH + nb;
    const bool valid = b < batch;

    const float* __restrict__ inb  = in  + (size_t)b * FLAT;
    float*       __restrict__ outb = out + (size_t)b * ROWLEN;
    float* smb = sm + nb * (F_PAD * D);

    // ---- Stage this warp's d-half of every row + stream flat output ----
    if (valid) {
        smb[27 * D + dh * HALF + lane]      = 0.f;   // zero pad-row half
        smb[27 * D + dh * HALF + 32 + lane] = 0.f;
        #pragma unroll 6
        for (int it = 0; it < F * 2; ++it) {          // 54 iters, 32 floats each
            const int f = it >> 1;
            const int d = dh * HALF + ((it & 1) << 5) + lane;
            const float v = inb[f * D + d];
            smb[sm_word(f, d)] = v;                   // conflict-free STS
            outb[f * D + d]    = v;                   // coalesced STG
        }
    }
    __syncwarp();

    // ---- Partial gram over this warp's d-half: lane<28 owns a 4x4 tile ----
    int ti = 0, tj = 0;
    float val[4][4];
    if (valid && lane < 28) {
        int l = lane, cnt = 7;
        while (l >= cnt) { l -= cnt; ++ti; --cnt; }
        tj = ti + l;

        unsigned long long acc[4][4];
        #pragma unroll
        for (int r = 0; r < 4; ++r)
            #pragma unroll
            for (int c = 0; c < 4; ++c) acc[r][c] = 0ull;

        const float* pi = smb + (4 * ti) * D;
        const float* pj = smb + (4 * tj) * D;

        const int c0 = dh * 16;
        #pragma unroll 2
        for (int c = c0; c < c0 + 16; ++c) {
            const int ci = (c ^ ti) << 2;
            const int cj = (c ^ tj) << 2;
            float4 ai4[4], aj4[4];
            #pragma unroll
            for (int r = 0; r < 4; ++r)
                ai4[r] = *reinterpret_cast<const float4*>(pi + r * D + ci);
            #pragma unroll
            for (int cc = 0; cc < 4; ++cc)
                aj4[cc] = *reinterpret_cast<const float4*>(pj + cc * D + cj);

            unsigned long long ailo[4], aihi[4], ajlo[4], ajhi[4];
            #pragma unroll
            for (int r = 0; r < 4; ++r) {
                ailo[r] = pack2(ai4[r].x, ai4[r].y);
                aihi[r] = pack2(ai4[r].z, ai4[r].w);
            }
            #pragma unroll
            for (int cc = 0; cc < 4; ++cc) {
                ajlo[cc] = pack2(aj4[cc].x, aj4[cc].y);
                ajhi[cc] = pack2(aj4[cc].z, aj4[cc].w);
            }
            #pragma unroll
            for (int r = 0; r < 4; ++r)
                #pragma unroll
                for (int cc = 0; cc < 4; ++cc) {
                    ffma2(acc[r][cc], ailo[r], ajlo[cc]);
                    ffma2(acc[r][cc], aihi[r], ajhi[cc]);
                }
        }
        #pragma unroll
        for (int r = 0; r < 4; ++r)
            #pragma unroll
            for (int cc = 0; cc < 4; ++cc) {
                float lo, hi;
                unpack2(acc[r][cc], lo, hi);
                val[r][cc] = lo + hi;
            }
    }
    __syncwarp();   // this warp's tile reads complete; its columns are scratch

    // ---- Warp dh==1 deposits 448 partials into its own dead columns ----
    // scratch word w (0..447) lives at smb[(w>>6)*128 + 64 + (w&63)]
    if (valid && lane < 28 && dh == 1) {
        #pragma unroll
        for (int r = 0; r < 4; ++r)
            #pragma unroll
            for (int cc = 0; cc < 4; ++cc) {
                const int w = (r * 4 + cc) * 28 + lane;
                smb[(w >> 6) * D + HALF + (w & 63)] = val[r][cc];
            }
    }
    __syncthreads();

    // ---- Warp dh==0 reduces, scatters triu into its own dead columns ----
    if (valid && lane < 28 && dh == 0) {
        #pragma unroll
        for (int r = 0; r < 4; ++r)
            #pragma unroll
            for (int cc = 0; cc < 4; ++cc) {
                const int w = (r * 4 + cc) * 28 + lane;
                val[r][cc] += smb[(w >> 6) * D + HALF + (w & 63)];
            }
        #pragma unroll
        for (int r = 0; r < 4; ++r) {
            const int i = 4 * ti + r;
            #pragma unroll
            for (int cc = 0; cc < 4; ++cc) {
                const int j = 4 * tj + cc;
                if (i < j && j < F) {
                    const int off = i * F - (i * (i + 1)) / 2 + (j - i - 1);
                    smb[(off >> 6) * D + (off & 63)] = val[r][cc];
                }
            }
        }
    }
    __syncwarp();

    // ---- Warp dh==0 stores the 351 triu floats coalesced ----
    if (valid && dh == 0) {
        float* outp = outb + FLAT;
        #pragma unroll
        for (int it = 0; it < (NPAIR + 31) / 32; ++it) {
            const int x = it * 32 + lane;
            if (x < NPAIR) outp[x] = smb[(x >> 6) * D + (x & 63)];
        }
    }
}

extern "C" void kernel_launch(void* const* d_in, const int* in_sizes, int n_in,
                              void* d_out, int out_size)
{
    const float* in = (const float*)d_in[0];
    float* out = (float*)d_out;
    const int batch = in_sizes[0] / FLAT;            // 16384
    const int grid = (batch + NBATCH - 1) / NBATCH;  // 5462
    fi_kernel<<<grid, THREADS>>>(in, out, batch);
}

// round 6
// speedup vs baseline: 1.3676x; 1.2936x over previous
#include <cuda_runtime.h>

// FeatureInteraction: B=16384, F=27, D=128
// out[b] = concat(embeddings[b].flatten() (3456), triu(E E^T, k=1) (351)) -> 3807 floats
//
// R6: break the streaming LDG->STS/STG dependence chain. Each lane batches 27
//     independent LDGs (MLP=27 covers ~600cyc DRAM latency), then drains to
//     smem + flat output. Compute (d-split warps, XOR-swizzled LDS.128, packed
//     fma.rn.f32x2, smem reduction) unchanged from R5.

static constexpr int F      = 27;
static constexpr int F_PAD  = 28;
static constexpr int D      = 128;
static constexpr int HALF   = 64;
static constexpr int FLAT   = F * D;              // 3456
static constexpr int NPAIR  = (F * (F - 1)) / 2;  // 351
static constexpr int ROWLEN = FLAT + NPAIR;       // 3807
static constexpr int NBATCH = 3;                  // batch elements per block
static constexpr int THREADS = NBATCH * 2 * 32;   // 192

__device__ __forceinline__ unsigned long long pack2(float x, float y) {
    unsigned long long r;
    asm("mov.b64 %0, {%1, %2};" : "=l"(r) : "f"(x), "f"(y));
    return r;
}
__device__ __forceinline__ void unpack2(unsigned long long v, float& x, float& y) {
    asm("mov.b64 {%0, %1}, %2;" : "=f"(x), "=f"(y) : "l"(v));
}
__device__ __forceinline__ void ffma2(unsigned long long& acc,
                                      unsigned long long a, unsigned long long b) {
    asm("fma.rn.f32x2 %0, %1, %2, %0;" : "+l"(acc) : "l"(a), "l"(b));
}

// Row f = words [f*128, f*128+128); 16B chunk c stored at slot c ^ (f>>2).
__device__ __forceinline__ int sm_word(int f, int d) {
    return f * D + ((((d >> 2) ^ (f >> 2)) << 2) | (d & 3));
}

__global__ void __launch_bounds__(THREADS, 4)
fi_kernel(const float* __restrict__ in, float* __restrict__ out, int batch)
{
    __shared__ float sm[NBATCH * F_PAD * D];      // 43008 B

    const int tid  = threadIdx.x;
    const int warp = tid >> 5;
    const int lane = tid & 31;
    const int nb   = warp >> 1;                   // batch slot in block
    const int dh   = warp & 1;                    // d-half owned by this warp
    const int b    = blockIdx.x * NBATCH + nb;
    const bool valid = b < batch;

    const float* __restrict__ inb  = in  + (size_t)b * FLAT;
    float*       __restrict__ outb = out + (size_t)b * ROWLEN;
    float* smb = sm + nb * (F_PAD * D);

    // ---- Stage this warp's d-half: two rounds of 27 batched independent LDGs
    if (valid) {
        smb[27 * D + dh * HALF + lane]      = 0.f;   // zero pad-row half
        smb[27 * D + dh * HALF + 32 + lane] = 0.f;

        const int d0 = dh * HALF + lane;             // this lane's two columns
        float v[F];
        #pragma unroll
        for (int f = 0; f < F; ++f) v[f] = inb[f * D + d0];          // 27 LDGs in flight
        #pragma unroll
        for (int f = 0; f < F; ++f) {
            smb[sm_word(f, d0)] = v[f];
            outb[f * D + d0]    = v[f];
        }
        #pragma unroll
        for (int f = 0; f < F; ++f) v[f] = inb[f * D + d0 + 32];     // next 27
        #pragma unroll
        for (int f = 0; f < F; ++f) {
            smb[sm_word(f, d0 + 32)] = v[f];
            outb[f * D + d0 + 32]    = v[f];
        }
    }
    __syncwarp();

    // ---- Partial gram over this warp's d-half: lane<28 owns a 4x4 tile ----
    int ti = 0, tj = 0;
    float val[4][4];
    if (valid && lane < 28) {
        int l = lane, cnt = 7;
        while (l >= cnt) { l -= cnt; ++ti; --cnt; }
        tj = ti + l;

        unsigned long long acc[4][4];
        #pragma unroll
        for (int r = 0; r < 4; ++r)
            #pragma unroll
            for (int c = 0; c < 4; ++c) acc[r][c] = 0ull;

        const float* pi = smb + (4 * ti) * D;
        const float* pj = smb + (4 * tj) * D;

        const int c0 = dh * 16;
        #pragma unroll 2
        for (int c = c0; c < c0 + 16; ++c) {
            const int ci = (c ^ ti) << 2;
            const int cj = (c ^ tj) << 2;
            float4 ai4[4], aj4[4];
            #pragma unroll
            for (int r = 0; r < 4; ++r)
                ai4[r] = *reinterpret_cast<const float4*>(pi + r * D + ci);
            #pragma unroll
            for (int cc = 0; cc < 4; ++cc)
                aj4[cc] = *reinterpret_cast<const float4*>(pj + cc * D + cj);

            unsigned long long ailo[4], aihi[4], ajlo[4], ajhi[4];
            #pragma unroll
            for (int r = 0; r < 4; ++r) {
                ailo[r] = pack2(ai4[r].x, ai4[r].y);
                aihi[r] = pack2(ai4[r].z, ai4[r].w);
            }
            #pragma unroll
            for (int cc = 0; cc < 4; ++cc) {
                ajlo[cc] = pack2(aj4[cc].x, aj4[cc].y);
                ajhi[cc] = pack2(aj4[cc].z, aj4[cc].w);
            }
            #pragma unroll
            for (int r = 0; r < 4; ++r)
                #pragma unroll
                for (int cc = 0; cc < 4; ++cc) {
                    ffma2(acc[r][cc], ailo[r], ajlo[cc]);
                    ffma2(acc[r][cc], aihi[r], ajhi[cc]);
                }
        }
        #pragma unroll
        for (int r = 0; r < 4; ++r)
            #pragma unroll
            for (int cc = 0; cc < 4; ++cc) {
                float lo, hi;
                unpack2(acc[r][cc], lo, hi);
                val[r][cc] = lo + hi;
            }
    }
    __syncwarp();   // this warp's tile reads complete; its columns are scratch

    // ---- Warp dh==1 deposits 448 partials into its own dead columns ----
    if (valid && lane < 28 && dh == 1) {
        #pragma unroll
        for (int r = 0; r < 4; ++r)
            #pragma unroll
            for (int cc = 0; cc < 4; ++cc) {
                const int w = (r * 4 + cc) * 28 + lane;
                smb[(w >> 6) * D + HALF + (w & 63)] = val[r][cc];
            }
    }
    __syncthreads();

    // ---- Warp dh==0 reduces, scatters triu into its own dead columns ----
    if (valid && lane < 28 && dh == 0) {
        #pragma unroll
        for (int r = 0; r < 4; ++r)
            #pragma unroll
            for (int cc = 0; cc < 4; ++cc) {
                const int w = (r * 4 + cc) * 28 + lane;
                val[r][cc] += smb[(w >> 6) * D + HALF + (w & 63)];
            }
        #pragma unroll
        for (int r = 0; r < 4; ++r) {
            const int i = 4 * ti + r;
            #pragma unroll
            for (int cc = 0; cc < 4; ++cc) {
                const int j = 4 * tj + cc;
                if (i < j && j < F) {
                    const int off = i * F - (i * (i + 1)) / 2 + (j - i - 1);
                    smb[(off >> 6) * D + (off & 63)] = val[r][cc];
                }
            }
        }
    }
    __syncwarp();

    // ---- Warp dh==0 stores the 351 triu floats coalesced ----
    if (valid && dh == 0) {
        float* outp = outb + FLAT;
        #pragma unroll
        for (int it = 0; it < (NPAIR + 31) / 32; ++it) {
            const int x = it * 32 + lane;
            if (x < NPAIR) outp[x] = smb[(x >> 6) * D + (x & 63)];
        }
    }
}

extern "C" void kernel_launch(void* const* d_in, const int* in_sizes, int n_in,
                              void* d_out, int out_size)
{
    const float* in = (const float*)d_in[0];
    float* out = (float*)d_out;
    const int batch = in_sizes[0] / FLAT;            // 16384
    const int grid = (batch + NBATCH - 1) / NBATCH;  // 5462
    fi_kernel<<<grid, THREADS>>>(in, out, batch);
}